// round 1
// baseline (speedup 1.0000x reference)
#include <cuda_runtime.h>
#include <math_constants.h>

// Problem constants
#define BB 4
#define SS 2048
#define DM 512
#define HH 8
#define DD 64
#define LEFTK 128
#define RIGHTK 128

// Scratch (allocation-free: __device__ globals)
__device__ float g_Q[BB * SS * DM];
__device__ float g_K[BB * SS * DM];
__device__ float g_V[BB * SS * DM];
__device__ float g_C[BB * SS * DM];
__device__ float g_meanV[BB * DM];

// ---------------------------------------------------------------------------
// SGEMM: C[M=8192, N=512] = A[M,512] @ W[512,512] + bias[512]
// BM=128, BN=128, BK=16, 256 threads, 8x8 per thread.
// ---------------------------------------------------------------------------
__global__ __launch_bounds__(256) void sgemm_bias_kernel(
    const float* __restrict__ A, const float* __restrict__ W,
    const float* __restrict__ bias, float* __restrict__ C)
{
    __shared__ __align__(16) float As[16][132];
    __shared__ __align__(16) float Bs[16][132];

    const int t  = threadIdx.x;
    const int tx = t & 15;
    const int ty = t >> 4;
    const int m0 = blockIdx.x * 128;
    const int n0 = blockIdx.y * 128;

    float acc[8][8];
#pragma unroll
    for (int i = 0; i < 8; i++)
#pragma unroll
        for (int j = 0; j < 8; j++) acc[i][j] = 0.f;

    // A loader mapping: row am = t>>1 (0..127), k offset ak = (t&1)*8
    const int am = t >> 1;
    const int ak = (t & 1) * 8;
    // B loader mapping: row br = t>>5 (0..7) and +8, col group bc = t&31
    const int br = t >> 5;
    const int bc = (t & 31) * 4;

    for (int k0 = 0; k0 < DM; k0 += 16) {
        float4 a0 = *(const float4*)&A[(size_t)(m0 + am) * DM + k0 + ak];
        float4 a1 = *(const float4*)&A[(size_t)(m0 + am) * DM + k0 + ak + 4];
        float4 b0 = *(const float4*)&W[(size_t)(k0 + br) * DM + n0 + bc];
        float4 b1 = *(const float4*)&W[(size_t)(k0 + br + 8) * DM + n0 + bc];

        As[ak + 0][am] = a0.x; As[ak + 1][am] = a0.y;
        As[ak + 2][am] = a0.z; As[ak + 3][am] = a0.w;
        As[ak + 4][am] = a1.x; As[ak + 5][am] = a1.y;
        As[ak + 6][am] = a1.z; As[ak + 7][am] = a1.w;
        *(float4*)&Bs[br][bc]     = b0;
        *(float4*)&Bs[br + 8][bc] = b1;
        __syncthreads();

#pragma unroll
        for (int kk = 0; kk < 16; kk++) {
            float a[8], b[8];
            *(float4*)&a[0] = *(const float4*)&As[kk][ty * 8];
            *(float4*)&a[4] = *(const float4*)&As[kk][ty * 8 + 4];
            *(float4*)&b[0] = *(const float4*)&Bs[kk][tx * 8];
            *(float4*)&b[4] = *(const float4*)&Bs[kk][tx * 8 + 4];
#pragma unroll
            for (int i = 0; i < 8; i++)
#pragma unroll
                for (int j = 0; j < 8; j++)
                    acc[i][j] += a[i] * b[j];
        }
        __syncthreads();
    }

#pragma unroll
    for (int i = 0; i < 8; i++) {
        const int m = m0 + ty * 8 + i;
#pragma unroll
        for (int j = 0; j < 8; j += 4) {
            const int n = n0 + tx * 8 + j;
            float4 o;
            o.x = acc[i][j]     + __ldg(&bias[n]);
            o.y = acc[i][j + 1] + __ldg(&bias[n + 1]);
            o.z = acc[i][j + 2] + __ldg(&bias[n + 2]);
            o.w = acc[i][j + 3] + __ldg(&bias[n + 3]);
            *(float4*)&C[(size_t)m * DM + n] = o;
        }
    }
}

// ---------------------------------------------------------------------------
// meanV[b, c] = (1/S) * sum_s V[b, s, c]   (needed for fully-masked rows:
// fp32 reference collapses those rows to a UNIFORM softmax over all S keys)
// ---------------------------------------------------------------------------
__global__ void meanv_kernel(const float* __restrict__ V, float* __restrict__ meanV)
{
    const int b = blockIdx.x;
    const int c = threadIdx.x;  // 512 threads
    const float* p = V + (size_t)b * SS * DM + c;
    float s = 0.f;
    for (int j = 0; j < SS; j++) s += p[(size_t)j * DM];
    meanV[b * DM + c] = s * (1.0f / (float)SS);
}

// ---------------------------------------------------------------------------
// Banded attention. 1 thread = 1 query (q, acc[64] in regs). A block of 128
// queries for one (b,h) sweeps the union key band with a warp-UNIFORM key
// index so all K/V shared loads are broadcasts. Online softmax in 8-key
// subtiles. Keys j valid iff j in [i-128, i+128] and j < x_len[b].
// ---------------------------------------------------------------------------
#define BQ 128
#define KCH 128
#define KST 68   // row stride in floats (16B-aligned for float4)

__global__ __launch_bounds__(128) void attn_kernel(
    const float* __restrict__ Q, const float* __restrict__ K,
    const float* __restrict__ V, const float* __restrict__ meanV,
    const int* __restrict__ xlen, float* __restrict__ C)
{
    extern __shared__ __align__(16) float sh[];
    float* Ks = sh;
    float* Vs = sh + KCH * KST;

    const int b  = blockIdx.z;
    const int h  = blockIdx.y;
    const int q0 = blockIdx.x * BQ;
    const int t  = threadIdx.x;
    const int i  = q0 + t;
    const int xl = xlen[b];

    float q[64];
    {
        const float* qp = Q + ((size_t)(b * SS + i)) * DM + h * DD;
#pragma unroll
        for (int d = 0; d < 64; d += 4) {
            float4 v4 = *(const float4*)&qp[d];
            q[d]     = v4.x * 0.125f;   // 1/sqrt(64)
            q[d + 1] = v4.y * 0.125f;
            q[d + 2] = v4.z * 0.125f;
            q[d + 3] = v4.w * 0.125f;
        }
    }
    float acc[64];
#pragma unroll
    for (int d = 0; d < 64; d++) acc[d] = 0.f;
    float m = -CUDART_INF_F, l = 0.f;

    const int jlo = max(0, i - LEFTK);
    const int jhi = min(min(SS, i + RIGHTK + 1), xl);  // exclusive end of valid keys
    const bool fully_masked = (jlo >= xl);

    const int cmin = max(0, q0 - LEFTK);
    int cmax = min(SS, q0 + BQ + RIGHTK);
    if (cmax > xl) cmax = xl;  // keys >= xl invalid for every thread

    for (int jc = cmin; jc < cmax; jc += KCH) {
        const int rows = min(KCH, cmax - jc);
        __syncthreads();
        for (int idx = t; idx < rows * 16; idx += BQ) {
            const int r  = idx >> 4;
            const int dq = (idx & 15) << 2;
            const size_t g = ((size_t)(b * SS + jc + r)) * DM + h * DD + dq;
            *(float4*)&Ks[r * KST + dq] = *(const float4*)&K[g];
            *(float4*)&Vs[r * KST + dq] = *(const float4*)&V[g];
        }
        __syncthreads();

        for (int j8 = jc; j8 < jc + rows; j8 += 8) {
            const int n8 = min(8, jc + rows - j8);  // uniform across block
            float e[8];
            float mloc = -CUDART_INF_F;
#pragma unroll
            for (int jj = 0; jj < 8; jj++) {
                e[jj] = -CUDART_INF_F;
                if (jj < n8) {
                    const float* kr = &Ks[(j8 - jc + jj) * KST];
                    float d0 = 0.f, d1 = 0.f;
#pragma unroll
                    for (int d = 0; d < 64; d += 8) {
                        float4 k4 = *(const float4*)&kr[d];
                        float4 k5 = *(const float4*)&kr[d + 4];
                        d0 += q[d]     * k4.x + q[d + 1] * k4.y
                            + q[d + 2] * k4.z + q[d + 3] * k4.w;
                        d1 += q[d + 4] * k5.x + q[d + 5] * k5.y
                            + q[d + 6] * k5.z + q[d + 7] * k5.w;
                    }
                    const int j = j8 + jj;
                    if (j >= jlo && j < jhi) e[jj] = d0 + d1;
                    mloc = fmaxf(mloc, e[jj]);
                }
            }
            const float mn = fmaxf(m, mloc);
            if (mn == -CUDART_INF_F) continue;  // nothing valid yet (no syncs inside)
            const float corr = __expf(m - mn);  // exp(-inf)=0 handles first tile
            m = mn;
            l *= corr;
#pragma unroll
            for (int d = 0; d < 64; d++) acc[d] *= corr;
#pragma unroll
            for (int jj = 0; jj < 8; jj++) {
                if (jj < n8) {  // n8 uniform -> no divergence
                    const float p = __expf(e[jj] - mn);  // invalid -> exp(-inf)=0
                    l += p;
                    const float* vr = &Vs[(j8 - jc + jj) * KST];
#pragma unroll
                    for (int d = 0; d < 64; d += 4) {
                        float4 v4 = *(const float4*)&vr[d];
                        acc[d]     += p * v4.x;
                        acc[d + 1] += p * v4.y;
                        acc[d + 2] += p * v4.z;
                        acc[d + 3] += p * v4.w;
                    }
                }
            }
        }
    }

    float* cp = C + ((size_t)(b * SS + i)) * DM + h * DD;
    if (fully_masked) {
        // fp32 reference: all energies collapse to exactly -1e30 -> uniform
        // softmax over ALL S keys -> ctx = mean of V over the sequence.
        const float* mv = meanV + b * DM + h * DD;
#pragma unroll
        for (int d = 0; d < 64; d += 4)
            *(float4*)&cp[d] = *(const float4*)&mv[d];
    } else {
        const float inv = 1.0f / l;
#pragma unroll
        for (int d = 0; d < 64; d += 4) {
            float4 o;
            o.x = acc[d] * inv;     o.y = acc[d + 1] * inv;
            o.z = acc[d + 2] * inv; o.w = acc[d + 3] * inv;
            *(float4*)&cp[d] = o;
        }
    }
}

// ---------------------------------------------------------------------------
// Launch
// ---------------------------------------------------------------------------
extern "C" void kernel_launch(void* const* d_in, const int* in_sizes, int n_in,
                              void* d_out, int out_size)
{
    const float* x    = (const float*)d_in[0];
    const float* Wq   = (const float*)d_in[1];
    const float* bq   = (const float*)d_in[2];
    const float* Wk   = (const float*)d_in[3];
    const float* bk   = (const float*)d_in[4];
    const float* Wv   = (const float*)d_in[5];
    const float* bv   = (const float*)d_in[6];
    const float* Wo   = (const float*)d_in[7];
    const float* bo   = (const float*)d_in[8];
    const int*   xlen = (const int*)d_in[9];
    float* out = (float*)d_out;

    float *Qp, *Kp, *Vp, *Cp, *Mp;
    cudaGetSymbolAddress((void**)&Qp, g_Q);
    cudaGetSymbolAddress((void**)&Kp, g_K);
    cudaGetSymbolAddress((void**)&Vp, g_V);
    cudaGetSymbolAddress((void**)&Cp, g_C);
    cudaGetSymbolAddress((void**)&Mp, g_meanV);

    const dim3 ggrid((BB * SS) / 128, DM / 128);  // 64 x 4
    sgemm_bias_kernel<<<ggrid, 256>>>(x, Wq, bq, Qp);
    sgemm_bias_kernel<<<ggrid, 256>>>(x, Wk, bk, Kp);
    sgemm_bias_kernel<<<ggrid, 256>>>(x, Wv, bv, Vp);

    meanv_kernel<<<BB, DM>>>(Vp, Mp);

    const int shbytes = 2 * KCH * KST * (int)sizeof(float);  // 69632
    cudaFuncSetAttribute(attn_kernel,
                         cudaFuncAttributeMaxDynamicSharedMemorySize, shbytes);
    attn_kernel<<<dim3(SS / BQ, HH, BB), BQ, shbytes>>>(Qp, Kp, Vp, Mp, xlen, Cp);

    sgemm_bias_kernel<<<ggrid, 256>>>(Cp, Wo, bo, out);
}